// round 17
// baseline (speedup 1.0000x reference)
#include <cuda_runtime.h>
#include <cuda_bf16.h>
#include <cstdint>

#define FIN 512
#define HID 64
#define NCLS 40
#define NMAX 100000
#define EMAX 1000000

// Scratch (no allocs allowed).
__device__ float g_buf1[6400000];
__device__ float g_buf2[6400000];
__device__ int   g_cnt[NMAX];
__device__ int   g_rowstart[NMAX + 1];
__device__ int   g_cursor[NMAX];
__device__ int   g_aux[1024];
__device__ int   g_auxs[1024];
__device__ int   g_csr_col[EMAX];
__device__ float g_csr_val[EMAX];

// ======================================================== CSR build
__global__ void csr_zero_cnt(int n) {
    int i = blockIdx.x * blockDim.x + threadIdx.x;
    if (i < n) g_cnt[i] = 0;
}
__global__ void csr_hist(const int* __restrict__ er, int E) {
    int e = blockIdx.x * blockDim.x + threadIdx.x;
    if (e < E) atomicAdd(&g_cnt[__ldg(er + e)], 1);
}
__global__ void csr_blocksum(int n) {
    __shared__ int sm[256];
    int i = blockIdx.x * 256 + threadIdx.x;
    int v = (i < n) ? g_cnt[i] : 0;
    sm[threadIdx.x] = v;
    __syncthreads();
    for (int o = 128; o; o >>= 1) {
        if (threadIdx.x < o) sm[threadIdx.x] += sm[threadIdx.x + o];
        __syncthreads();
    }
    if (threadIdx.x == 0) g_aux[blockIdx.x] = sm[0];
}
__global__ void csr_scan_aux(int nb) {
    __shared__ int sm[1024];
    int t = threadIdx.x;
    int v = (t < nb) ? g_aux[t] : 0;
    sm[t] = v;
    __syncthreads();
    for (int o = 1; o < 1024; o <<= 1) {
        int a = (t >= o) ? sm[t - o] : 0;
        __syncthreads();
        sm[t] += a;
        __syncthreads();
    }
    if (t < nb) g_auxs[t] = sm[t] - v;
}
__global__ void csr_scan_final(int n, int E) {
    __shared__ int sm[256];
    int t = threadIdx.x;
    int i = blockIdx.x * 256 + t;
    int v = (i < n) ? g_cnt[i] : 0;
    sm[t] = v;
    __syncthreads();
    for (int o = 1; o < 256; o <<= 1) {
        int a = (t >= o) ? sm[t - o] : 0;
        __syncthreads();
        sm[t] += a;
        __syncthreads();
    }
    int base = g_auxs[blockIdx.x];
    int excl = base + sm[t] - v;
    if (i < n) {
        g_rowstart[i] = excl;
        g_cursor[i] = excl;
    }
    if (i == n - 1) g_rowstart[n] = E;
}
__global__ void csr_scatter(const int* __restrict__ er, const int* __restrict__ ec,
                            const float* __restrict__ ev, int E) {
    int e = blockIdx.x * blockDim.x + threadIdx.x;
    if (e >= E) return;
    int r = __ldg(er + e);
    int p = atomicAdd(&g_cursor[r], 1);
    g_csr_col[p] = __ldg(ec + e);
    g_csr_val[p] = __ldg(ev + e);
}

// ============ GEMM1: Y = x @ W1 (mma.sync bf16x3, preconverted hi/lo smem)
// Tile 64(M) x 64(N), 256 threads, 4 CTAs/SM target.
__device__ __forceinline__ void mma_bf16(float c[4], const unsigned a[4], const unsigned b[2]) {
    asm volatile(
        "mma.sync.aligned.m16n8k16.row.col.f32.bf16.bf16.f32 "
        "{%0,%1,%2,%3}, {%4,%5,%6,%7}, {%8,%9}, {%0,%1,%2,%3};"
        : "+f"(c[0]), "+f"(c[1]), "+f"(c[2]), "+f"(c[3])
        : "r"(a[0]), "r"(a[1]), "r"(a[2]), "r"(a[3]), "r"(b[0]), "r"(b[1]));
}
// pack (even,odd) fp32 pair into bf16x2 hi + bf16x2 lo (residual)
__device__ __forceinline__ void split2(float ve, float vo, unsigned &h, unsigned &l) {
    unsigned hh;
    asm("cvt.rn.bf16x2.f32 %0, %1, %2;" : "=r"(hh) : "f"(vo), "f"(ve));
    float fe = __uint_as_float(hh << 16);
    float fo = __uint_as_float(hh & 0xffff0000u);
    float re = ve - fe;
    float ro = vo - fo;
    unsigned ll;
    asm("cvt.rn.bf16x2.f32 %0, %1, %2;" : "=r"(ll) : "f"(ro), "f"(re));
    h = hh; l = ll;
}

#define ASTR 20  // uint32 stride per row (16 kpairs + 4 pad): conflict-free compute loads

__global__ __launch_bounds__(256, 4) void gemm1_kernel(const float* __restrict__ X,
                                                       const float* __restrict__ W,
                                                       int nrows) {
    __shared__ unsigned Ah[64 * ASTR], Al[64 * ASTR];
    __shared__ unsigned Bh[64 * ASTR], Bl[64 * ASTR];
    const int tid = threadIdx.x;
    const int bm = blockIdx.x * 64;
    const int warp = tid >> 5, lane = tid & 31;
    const int g = lane >> 2, tg = lane & 3;
    const int wm = (warp >> 1) * 16;      // 4 m-groups of 16 rows
    const int wn = (warp & 1) * 32;       // 2 n-groups of 32 cols
    const int bn = tid & 63;              // B n this thread loads
    const int bkp0 = tid >> 6;            // B kpair sub-index (0..3)

    float c[4][4];
#pragma unroll
    for (int b = 0; b < 4; ++b)
#pragma unroll
        for (int d = 0; d < 4; ++d) c[b][d] = 0.f;

    float4 ra[2];   // A: 64 rows x 32 k = 512 float4, 2/thread
    float rb[8];
    // prologue: raw loads for tile kt=0
#pragma unroll
    for (int p = 0; p < 2; ++p) {
        int i = p * 256 + tid;
        int gr = bm + (i >> 3);
        int kq = (i & 7) * 4;
        ra[p] = (gr < nrows) ? __ldg((const float4*)(X + (size_t)gr * FIN + kq))
                             : make_float4(0.f, 0.f, 0.f, 0.f);
    }
#pragma unroll
    for (int it = 0; it < 4; ++it) {
        int kp = it * 4 + bkp0;
        rb[2 * it]     = __ldg(W + (size_t)(2 * kp) * HID + bn);
        rb[2 * it + 1] = __ldg(W + (size_t)(2 * kp + 1) * HID + bn);
    }

    for (int kt = 0; kt < FIN / 32; ++kt) {
        // convert + store current tile
#pragma unroll
        for (int p = 0; p < 2; ++p) {
            int i = p * 256 + tid;
            int r = i >> 3;
            int kq = (i & 7) * 4;
            unsigned h0, l0, h1, l1;
            split2(ra[p].x, ra[p].y, h0, l0);
            split2(ra[p].z, ra[p].w, h1, l1);
            int o = r * ASTR + kq / 2;
            Ah[o] = h0; Ah[o + 1] = h1;
            Al[o] = l0; Al[o + 1] = l1;
        }
#pragma unroll
        for (int it = 0; it < 4; ++it) {
            int kp = it * 4 + bkp0;
            unsigned h, l;
            split2(rb[2 * it], rb[2 * it + 1], h, l);
            Bh[bn * ASTR + kp] = h;
            Bl[bn * ASTR + kp] = l;
        }
        __syncthreads();
        // prefetch next tile raw
        if (kt + 1 < FIN / 32) {
            int k0 = (kt + 1) * 32;
#pragma unroll
            for (int p = 0; p < 2; ++p) {
                int i = p * 256 + tid;
                int gr = bm + (i >> 3);
                int kq = (i & 7) * 4;
                ra[p] = (gr < nrows) ? __ldg((const float4*)(X + (size_t)gr * FIN + k0 + kq))
                                     : make_float4(0.f, 0.f, 0.f, 0.f);
            }
#pragma unroll
            for (int it = 0; it < 4; ++it) {
                int kp = it * 4 + bkp0;
                rb[2 * it]     = __ldg(W + (size_t)(k0 + 2 * kp) * HID + bn);
                rb[2 * it + 1] = __ldg(W + (size_t)(k0 + 2 * kp + 1) * HID + bn);
            }
        }
        // compute: 2 x k16
#pragma unroll
        for (int kk = 0; kk < 2; ++kk) {
            const int kb = kk * 8;
            unsigned ah[4], al[4];
            {
                int r0 = (wm + g) * ASTR + kb + tg;
                ah[0] = Ah[r0];                al[0] = Al[r0];
                ah[1] = Ah[r0 + 8 * ASTR];     al[1] = Al[r0 + 8 * ASTR];
                ah[2] = Ah[r0 + 4];            al[2] = Al[r0 + 4];
                ah[3] = Ah[r0 + 8 * ASTR + 4]; al[3] = Al[r0 + 8 * ASTR + 4];
            }
#pragma unroll
            for (int nt = 0; nt < 4; ++nt) {
                int nb0 = (wn + nt * 8 + g) * ASTR + kb + tg;
                unsigned bh[2], bl[2];
                bh[0] = Bh[nb0];     bh[1] = Bh[nb0 + 4];
                bl[0] = Bl[nb0];     bl[1] = Bl[nb0 + 4];
                mma_bf16(c[nt], ah, bh);
                mma_bf16(c[nt], al, bh);
                mma_bf16(c[nt], ah, bl);
            }
        }
        __syncthreads();
    }

#pragma unroll
    for (int nt = 0; nt < 4; ++nt) {
        int r0 = bm + wm + g;
        int cc = wn + nt * 8 + 2 * tg;
        if (r0 < nrows)
            *(float2*)(g_buf1 + (size_t)r0 * HID + cc) = make_float2(c[nt][0], c[nt][1]);
        if (r0 + 8 < nrows)
            *(float2*)(g_buf1 + (size_t)(r0 + 8) * HID + cc) = make_float2(c[nt][2], c[nt][3]);
    }
}

// ---- JAX partitionable threefry (key=42): element j -> counts (0, j), fold = o0^o1
__device__ __forceinline__ unsigned tf_draw(unsigned j) {
    unsigned x0 = 0u, x1 = j;
    const unsigned ks0 = 0u, ks1 = 42u, ks2 = 0x1BD11BDAu ^ 42u;
    x0 += ks0; x1 += ks1;
#define TF_ROUND(r) { x0 += x1; x1 = __funnelshift_l(x1, x1, r); x1 ^= x0; }
    TF_ROUND(13) TF_ROUND(15) TF_ROUND(26) TF_ROUND(6)
    x0 += ks1; x1 += ks2 + 1u;
    TF_ROUND(17) TF_ROUND(29) TF_ROUND(16) TF_ROUND(24)
    x0 += ks2; x1 += ks0 + 2u;
    TF_ROUND(13) TF_ROUND(15) TF_ROUND(26) TF_ROUND(6)
    x0 += ks0; x1 += ks1 + 3u;
    TF_ROUND(17) TF_ROUND(29) TF_ROUND(16) TF_ROUND(24)
    x0 += ks1; x1 += ks2 + 4u;
    TF_ROUND(13) TF_ROUND(15) TF_ROUND(26) TF_ROUND(6)
    x0 += ks2; x1 += ks0 + 5u;
#undef TF_ROUND
    return x0 ^ x1;
}

// ---- SpMM1 gather + bias + relu + dropout epilogue: one warp per row, MLP-2
__global__ __launch_bounds__(256) void spmm1_gather(const float* __restrict__ b1, int nrows) {
    int warp = threadIdx.x >> 5;
    int lane = threadIdx.x & 31;
    int row = blockIdx.x * 8 + warp;
    if (row >= nrows) return;
    int s = g_rowstart[row], e = g_rowstart[row + 1];
    float a0 = 0.f, a1 = 0.f;
    int l2 = lane * 2;
    int i = s;
    for (; i + 1 < e; i += 2) {
        int c0 = g_csr_col[i], c1 = g_csr_col[i + 1];
        float v0 = g_csr_val[i], v1 = g_csr_val[i + 1];
        float2 f0 = *(const float2*)(g_buf1 + (size_t)c0 * HID + l2);
        float2 f1 = *(const float2*)(g_buf1 + (size_t)c1 * HID + l2);
        a0 += v0 * f0.x + v1 * f1.x;
        a1 += v0 * f0.y + v1 * f1.y;
    }
    if (i < e) {
        int c0 = g_csr_col[i];
        float v0 = g_csr_val[i];
        float2 f0 = *(const float2*)(g_buf1 + (size_t)c0 * HID + l2);
        a0 += v0 * f0.x;
        a1 += v0 * f0.y;
    }
    float2 bb = *(const float2*)(b1 + l2);
    unsigned j0 = (unsigned)row * HID + l2;
    a0 = fmaxf(a0 + bb.x, 0.f);
    a0 = (tf_draw(j0) >> 31) ? 0.f : a0 * 2.f;
    a1 = fmaxf(a1 + bb.y, 0.f);
    a1 = (tf_draw(j0 + 1u) >> 31) ? 0.f : a1 * 2.f;
    *(float2*)(g_buf2 + (size_t)row * HID + l2) = make_float2(a0, a1);
}

// ---------------- GEMM2: G = h @ W2 (h already bias/relu/dropout'd)
__global__ __launch_bounds__(320) void gemm2_kernel(const float* __restrict__ W2, int nrows) {
    __shared__ float sH[128 * 68];
    __shared__ float sW[HID * NCLS];
    const int tid = threadIdx.x;
    const int bm = blockIdx.x * 128;
    for (int i = tid; i < HID * NCLS; i += 320) sW[i] = __ldg(W2 + i);
    for (int i = tid; i < 2048; i += 320) {
        int r = i >> 4, c4 = (i & 15) * 4, gr = bm + r;
        float4 v = (gr < nrows) ? *(const float4*)(g_buf2 + (size_t)gr * HID + c4)
                                : make_float4(0.f, 0.f, 0.f, 0.f);
        *(float4*)(sH + r * 68 + c4) = v;
    }
    __syncthreads();
    const int rg = tid / 10;
    const int cg = tid - rg * 10;
    float acc[4][4];
#pragma unroll
    for (int a = 0; a < 4; ++a)
#pragma unroll
        for (int b = 0; b < 4; ++b) acc[a][b] = 0.f;
#pragma unroll 8
    for (int k = 0; k < HID; ++k) {
        float4 w = *(const float4*)(sW + k * NCLS + cg * 4);
#pragma unroll
        for (int jr = 0; jr < 4; ++jr) {
            float a = sH[(rg * 4 + jr) * 68 + k];
            acc[jr][0] += a * w.x; acc[jr][1] += a * w.y;
            acc[jr][2] += a * w.z; acc[jr][3] += a * w.w;
        }
    }
#pragma unroll
    for (int jr = 0; jr < 4; ++jr) {
        int gr = bm + rg * 4 + jr;
        if (gr < nrows)
            *(float4*)(g_buf1 + (size_t)gr * NCLS + cg * 4) =
                make_float4(acc[jr][0], acc[jr][1], acc[jr][2], acc[jr][3]);
    }
}

// ------- SpMM2 gather fused with +b2 and log_softmax: one warp per row, MLP-2
__global__ __launch_bounds__(256) void spmm2_lsm(const float* __restrict__ b2,
                                                 float* __restrict__ out, int nrows) {
    int warp = threadIdx.x >> 5;
    int lane = threadIdx.x & 31;
    int row = blockIdx.x * 8 + warp;
    if (row >= nrows) return;
    int s = g_rowstart[row], e = g_rowstart[row + 1];
    bool act = lane < 20;
    int l2 = lane * 2;
    float a0 = 0.f, a1 = 0.f;
    int i = s;
    for (; i + 1 < e; i += 2) {
        int c0 = g_csr_col[i], c1 = g_csr_col[i + 1];
        float v0 = g_csr_val[i], v1 = g_csr_val[i + 1];
        if (act) {
            float2 f0 = *(const float2*)(g_buf1 + (size_t)c0 * NCLS + l2);
            float2 f1 = *(const float2*)(g_buf1 + (size_t)c1 * NCLS + l2);
            a0 += v0 * f0.x + v1 * f1.x;
            a1 += v0 * f0.y + v1 * f1.y;
        }
    }
    if (i < e) {
        int c0 = g_csr_col[i];
        float v0 = g_csr_val[i];
        if (act) {
            float2 f0 = *(const float2*)(g_buf1 + (size_t)c0 * NCLS + l2);
            a0 += v0 * f0.x;
            a1 += v0 * f0.y;
        }
    }
    if (act) {
        a0 += __ldg(b2 + l2);
        a1 += __ldg(b2 + l2 + 1);
    } else {
        a0 = a1 = -3.4e38f;
    }
    float m = fmaxf(a0, a1);
#pragma unroll
    for (int o = 16; o; o >>= 1) m = fmaxf(m, __shfl_xor_sync(0xffffffffu, m, o));
    float sum = act ? (expf(a0 - m) + expf(a1 - m)) : 0.f;
#pragma unroll
    for (int o = 16; o; o >>= 1) sum += __shfl_xor_sync(0xffffffffu, sum, o);
    float L = m + logf(sum);
    if (act)
        *(float2*)(out + (size_t)row * NCLS + l2) = make_float2(a0 - L, a1 - L);
}

// ---------------------------------------------------------------- launcher
extern "C" void kernel_launch(void* const* d_in, const int* in_sizes, int n_in,
                              void* d_out, int out_size) {
    const float* x  = (const float*)d_in[0];
    const float* ev = (const float*)d_in[1];
    const float* W1 = (const float*)d_in[2];
    const float* b1 = (const float*)d_in[3];
    const float* W2 = (const float*)d_in[4];
    const float* b2 = (const float*)d_in[5];
    const int*   er = (const int*)d_in[6];
    const int*   ec = (const int*)d_in[7];
    const int nrows = in_sizes[0] / FIN;  // 100000
    const int E = in_sizes[1];            // 1000000
    float* out = (float*)d_out;

    const int NB = (nrows + 255) / 256;
    // launch index 3 (ncu capture slot) = gemm1_kernel
    csr_zero_cnt<<<NB, 256>>>(nrows);
    csr_hist<<<(E + 255) / 256, 256>>>(er, E);
    csr_blocksum<<<NB, 256>>>(nrows);
    gemm1_kernel<<<(nrows + 63) / 64, 256>>>(x, W1, nrows);
    csr_scan_aux<<<1, 1024>>>(NB);
    csr_scan_final<<<NB, 256>>>(nrows, E);
    csr_scatter<<<(E + 255) / 256, 256>>>(er, ec, ev, E);
    spmm1_gather<<<(nrows + 7) / 8, 256>>>(b1, nrows);
    gemm2_kernel<<<(nrows + 127) / 128, 320>>>(W2, nrows);
    spmm2_lsm<<<(nrows + 7) / 8, 256>>>(b2, out, nrows);
}